// round 4
// baseline (speedup 1.0000x reference)
#include <cuda_runtime.h>
#include <cuda_bf16.h>

// STSEarlyFusionConcat: out (1, 2C, D, H, W) fp32
//   out[c,d,h,w]    = (w>=d) ? x[c,h,w]   : 0    for c in [0,C)
//   out[C+c,d,h,w]  = (w>=d) ? y[c,h,w-d] : 0    for c in [0,C)
// B=1, C=32, H=96, W=192, D=64.  HBM-write-bound: 302 MB out.
// R4: one block per contiguous (c2,d) output plane (72KB). Every block-wide
// store wave is 4KB contiguous; each block emits one sequential 72KB stream
// -> DRAM row-buffer friendly. d is block-uniform.

namespace {
constexpr int C   = 32;
constexpr int H   = 96;
constexpr int W   = 192;
constexpr int D   = 64;
constexpr int W4  = W / 4;                         // 48
constexpr int PLANE4 = H * W4;                     // 4608 float4 per plane
constexpr int TPB  = 256;
constexpr int KPT  = PLANE4 / TPB;                 // 18 float4 per thread
constexpr int NPLANES = 2 * C * D;                 // 4096 blocks
}

__global__ __launch_bounds__(TPB)
void stsef_kernel(const float* __restrict__ x,
                  const float* __restrict__ y,
                  float4* __restrict__ out)
{
    unsigned p  = blockIdx.x;        // plane = (c2, d)
    unsigned c2 = p >> 6;            // p / D
    int      d  = (int)(p & 63);     // p % D   (block-uniform)
    unsigned t  = threadIdx.x;

    float4* op = out + (size_t)p * PLANE4;

    if (c2 < C) {
        // cost_x plane: masked copy of x channel plane (same (h,w) layout)
        const float4* xp = reinterpret_cast<const float4*>(x + (size_t)c2 * H * W);
#pragma unroll
        for (int k = 0; k < KPT; k++) {
            unsigned i  = t + k * TPB;
            int w0 = (int)(i % W4) * 4;
            float4 v = __ldg(xp + i);
            v.x = (w0 + 0 >= d) ? v.x : 0.0f;
            v.y = (w0 + 1 >= d) ? v.y : 0.0f;
            v.z = (w0 + 2 >= d) ? v.z : 0.0f;
            v.w = (w0 + 3 >= d) ? v.w : 0.0f;
            __stcs(op + i, v);
        }
    } else {
        // cost_y plane: row-shifted y channel; load predicate == zero mask
        const float* yb = y + (size_t)(c2 - C) * H * W;
#pragma unroll
        for (int k = 0; k < KPT; k++) {
            unsigned i  = t + k * TPB;
            unsigned h  = i / W4;
            int b0 = (int)(i % W4) * 4 - d;
            const float* row = yb + h * W;
            float4 v;
            v.x = (b0 + 0 >= 0) ? __ldg(row + b0 + 0) : 0.0f;
            v.y = (b0 + 1 >= 0) ? __ldg(row + b0 + 1) : 0.0f;
            v.z = (b0 + 2 >= 0) ? __ldg(row + b0 + 2) : 0.0f;
            v.w = (b0 + 3 >= 0) ? __ldg(row + b0 + 3) : 0.0f;
            __stcs(op + i, v);
        }
    }
}

extern "C" void kernel_launch(void* const* d_in, const int* in_sizes, int n_in,
                              void* d_out, int out_size)
{
    const float* x = (const float*)d_in[0];
    const float* y = (const float*)d_in[1];
    float4* out = (float4*)d_out;

    stsef_kernel<<<NPLANES, TPB>>>(x, y, out);
}